// round 1
// baseline (speedup 1.0000x reference)
#include <cuda_runtime.h>
#include <cuda_bf16.h>

// NEP descriptor: E edges -> scatter-reduce into N atoms.
// Plan: zero scratch -> per-edge compute + 74 atomicAdds into L2-resident
// __device__ scratch -> per-atom finalize (invariants) into d_out.

#define NUM_TYPES 4
#define NR 11          // N_MAX_RADIAL+1 (also BASIS_RADIAL+1)
#define NA 7           // N_MAX_ANGULAR+1
#define BA 9           // BASIS_ANGULAR+1
#define MAX_ATOMS 50000
#define SSTRIDE 76     // 11 radial + 21 vec + 42 tensor = 74, padded to 76

__device__ float g_scratch[MAX_ATOMS * SSTRIDE];
__device__ int   g_idx64;   // 1 if edge_index/types are int64, 0 if int32

__global__ void detect_dtype_kernel(const int* __restrict__ ei32) {
    // int64 values < 2^31 viewed as int32 pairs: every odd word is 0.
    // True int32 index data (values in [0,50000)) has ~0 chance of 16 zeros.
    int ok = 1;
    #pragma unroll
    for (int k = 1; k < 32; k += 2)
        if (ei32[k] != 0) ok = 0;
    g_idx64 = ok;
}

__global__ void zero_kernel(int n) {
    int i = blockIdx.x * blockDim.x + threadIdx.x;
    if (i < n) g_scratch[i] = 0.0f;
}

__global__ __launch_bounds__(256)
void edge_kernel(const void* __restrict__ edge_index,
                 const float* __restrict__ edge_length,
                 const float* __restrict__ edge_vec,
                 const void* __restrict__ types,
                 const float* __restrict__ c_radial,
                 const float* __restrict__ c_angular,
                 int E)
{
    // Shared coefficient tables, pair-minor so lanes with different type
    // pairs hit distinct banks (16 consecutive words -> conflict-free).
    __shared__ float crs[NR * NR * 16];   // [(b*11+n)*16 + pair]
    __shared__ float cas[BA * NA * 16];   // [(b*7+n)*16 + pair]

    for (int i = threadIdx.x; i < 16 * NR * NR; i += blockDim.x) {
        int pair = i / (NR * NR);
        int nb   = i % (NR * NR);
        int n = nb / NR, b = nb % NR;
        crs[(b * NR + n) * 16 + pair] = c_radial[i];
    }
    for (int i = threadIdx.x; i < 16 * NA * BA; i += blockDim.x) {
        int pair = i / (NA * BA);
        int nb   = i % (NA * BA);
        int n = nb / BA, b = nb % BA;
        cas[(b * NA + n) * 16 + pair] = c_angular[i];
    }
    __syncthreads();

    int e = blockIdx.x * blockDim.x + threadIdx.x;
    if (e >= E) return;

    int row, col, ti, tj;
    if (g_idx64) {
        const long long* ei = (const long long*)edge_index;
        const long long* ty = (const long long*)types;
        row = (int)ei[e];
        col = (int)ei[E + e];
        ti = (int)ty[row]; tj = (int)ty[col];
    } else {
        const int* ei = (const int*)edge_index;
        const int* ty = (const int*)types;
        row = ei[e];
        col = ei[E + e];
        ti = ty[row]; tj = ty[col];
    }
    int pair = ti * NUM_TYPES + tj;

    float d = edge_length[e];
    float s = d * 0.2f;                   // d / CUTOFF
    float x = 2.0f * s - 1.0f;
    float denom = 1.0f - s * s;
    float cut = (s < 1.0f) ? expf(1.0f - 1.0f / denom) : 0.0f;

    // Chebyshev T_0..T_10 (angular reuses T_0..T_8), scaled by envelope
    float T[NR];
    T[0] = 1.0f; T[1] = x;
    #pragma unroll
    for (int k = 2; k < NR; k++) T[k] = 2.0f * x * T[k - 1] - T[k - 2];
    #pragma unroll
    for (int k = 0; k < NR; k++) T[k] *= cut;

    float* base = g_scratch + row * SSTRIDE;

    // ---- radial features: 11 outputs, 11 basis ----
    #pragma unroll
    for (int n = 0; n < NR; n++) {
        float acc = 0.0f;
        #pragma unroll
        for (int b = 0; b < NR; b++)
            acc = fmaf(T[b], crs[(b * NR + n) * 16 + pair], acc);
        atomicAdd(base + n, acc);
    }

    // ---- angular features: 7 outputs, 9 basis ----
    float af[NA];
    #pragma unroll
    for (int n = 0; n < NA; n++) {
        float acc = 0.0f;
        #pragma unroll
        for (int b = 0; b < BA; b++)
            acc = fmaf(T[b], cas[(b * NA + n) * 16 + pair], acc);
        af[n] = acc;
    }

    float vx = edge_vec[e * 3 + 0];
    float vy = edge_vec[e * 3 + 1];
    float vz = edge_vec[e * 3 + 2];
    float inv = 1.0f / fmaxf(d, 1e-8f);
    float ux = vx * inv, uy = vy * inv, uz = vz * inv;

    // quad (symmetric, NOT traceless here since edge_vec isn't unit-norm)
    float qxx = 1.5f * ux * ux - 0.5f;
    float qyy = 1.5f * uy * uy - 0.5f;
    float qzz = 1.5f * uz * uz - 0.5f;
    float qxy = 1.5f * ux * uy;
    float qxz = 1.5f * ux * uz;
    float qyz = 1.5f * uy * uz;

    #pragma unroll
    for (int n = 0; n < NA; n++) {
        float f = af[n];
        atomicAdd(base + 11 + n * 3 + 0, f * ux);
        atomicAdd(base + 11 + n * 3 + 1, f * uy);
        atomicAdd(base + 11 + n * 3 + 2, f * uz);
        atomicAdd(base + 32 + n * 6 + 0, f * qxx);
        atomicAdd(base + 32 + n * 6 + 1, f * qyy);
        atomicAdd(base + 32 + n * 6 + 2, f * qzz);
        atomicAdd(base + 32 + n * 6 + 3, f * qxy);
        atomicAdd(base + 32 + n * 6 + 4, f * qxz);
        atomicAdd(base + 32 + n * 6 + 5, f * qyz);
    }
}

__global__ void finalize_kernel(float* __restrict__ out, int N)
{
    int a = blockIdx.x * blockDim.x + threadIdx.x;
    if (a >= N) return;
    const float* sc = g_scratch + a * SSTRIDE;
    float* o = out + a * 25;

    #pragma unroll
    for (int n = 0; n < NR; n++) o[n] = sc[n];

    #pragma unroll
    for (int n = 0; n < NA; n++) {
        float vx = sc[11 + n * 3 + 0];
        float vy = sc[11 + n * 3 + 1];
        float vz = sc[11 + n * 3 + 2];
        o[11 + n] = vx * vx + vy * vy + vz * vz;
    }
    #pragma unroll
    for (int n = 0; n < NA; n++) {
        float xx = sc[32 + n * 6 + 0];
        float yy = sc[32 + n * 6 + 1];
        float zz = sc[32 + n * 6 + 2];
        float xy = sc[32 + n * 6 + 3];
        float xz = sc[32 + n * 6 + 4];
        float yz = sc[32 + n * 6 + 5];
        o[18 + n] = xx * xx + yy * yy + zz * zz
                  + 2.0f * (xy * xy + xz * xz + yz * yz);
    }
}

extern "C" void kernel_launch(void* const* d_in, const int* in_sizes, int n_in,
                              void* d_out, int out_size)
{
    const void*  edge_index  = d_in[0];
    const float* edge_length = (const float*)d_in[1];
    const float* edge_vec    = (const float*)d_in[2];
    // d_in[3] = num_atoms scalar (unused; N derived from out_size)
    const void*  types       = d_in[4];
    const float* c_radial    = (const float*)d_in[5];
    const float* c_angular   = (const float*)d_in[6];

    int E = in_sizes[1];        // edge_length element count
    int N = out_size / 25;

    detect_dtype_kernel<<<1, 1>>>((const int*)edge_index);

    int zn = N * SSTRIDE;
    zero_kernel<<<(zn + 511) / 512, 512>>>(zn);

    edge_kernel<<<(E + 255) / 256, 256>>>(edge_index, edge_length, edge_vec,
                                          types, c_radial, c_angular, E);

    finalize_kernel<<<(N + 255) / 256, 256>>>((float*)d_out, N);
}

// round 2
// speedup vs baseline: 3.1008x; 3.1008x over previous
#include <cuda_runtime.h>
#include <cuda_bf16.h>

// NEP descriptor: E edges -> scatter-reduce into N atoms.
// R2: replace 74 scalar atomicAdds/edge with 19x red.global.add.v4.f32.

#define NUM_TYPES 4
#define NR 11          // N_MAX_RADIAL+1 (also BASIS_RADIAL+1)
#define NA 7           // N_MAX_ANGULAR+1
#define BA 9           // BASIS_ANGULAR+1
#define MAX_ATOMS 50000
#define SSTRIDE 76     // 11 radial + 21 vec + 42 tensor = 74, pad to 76 (=19*4)

__device__ __align__(16) float g_scratch[MAX_ATOMS * SSTRIDE];
__device__ int   g_idx64;   // 1 if edge_index/types are int64, 0 if int32

__device__ __forceinline__ void red_add_v4(float* p, float a, float b, float c, float d) {
    asm volatile("red.global.add.v4.f32 [%0], {%1, %2, %3, %4};"
                 :: "l"(p), "f"(a), "f"(b), "f"(c), "f"(d) : "memory");
}

__global__ void detect_dtype_kernel(const int* __restrict__ ei32) {
    // int64 values < 2^31 viewed as int32 pairs: every odd word is 0.
    int ok = 1;
    #pragma unroll
    for (int k = 1; k < 32; k += 2)
        if (ei32[k] != 0) ok = 0;
    g_idx64 = ok;
}

__global__ void zero_kernel(int n4) {
    int i = blockIdx.x * blockDim.x + threadIdx.x;
    if (i < n4)
        ((float4*)g_scratch)[i] = make_float4(0.f, 0.f, 0.f, 0.f);
}

__global__ __launch_bounds__(256)
void edge_kernel(const void* __restrict__ edge_index,
                 const float* __restrict__ edge_length,
                 const float* __restrict__ edge_vec,
                 const void* __restrict__ types,
                 const float* __restrict__ c_radial,
                 const float* __restrict__ c_angular,
                 int E)
{
    // Shared coefficient tables, pair-minor so lanes with different type
    // pairs hit distinct banks (16 consecutive words -> conflict-free).
    __shared__ float crs[NR * NR * 16];   // [(b*11+n)*16 + pair]
    __shared__ float cas[BA * NA * 16];   // [(b*7+n)*16 + pair]

    for (int i = threadIdx.x; i < 16 * NR * NR; i += blockDim.x) {
        int pair = i / (NR * NR);
        int nb   = i % (NR * NR);
        int n = nb / NR, b = nb % NR;
        crs[(b * NR + n) * 16 + pair] = c_radial[i];
    }
    for (int i = threadIdx.x; i < 16 * NA * BA; i += blockDim.x) {
        int pair = i / (NA * BA);
        int nb   = i % (NA * BA);
        int n = nb / BA, b = nb % BA;
        cas[(b * NA + n) * 16 + pair] = c_angular[i];
    }
    __syncthreads();

    int e = blockIdx.x * blockDim.x + threadIdx.x;
    if (e >= E) return;

    int row, col, ti, tj;
    if (g_idx64) {
        const long long* ei = (const long long*)edge_index;
        const long long* ty = (const long long*)types;
        row = (int)ei[e];
        col = (int)ei[E + e];
        ti = (int)ty[row]; tj = (int)ty[col];
    } else {
        const int* ei = (const int*)edge_index;
        const int* ty = (const int*)types;
        row = ei[e];
        col = ei[E + e];
        ti = ty[row]; tj = ty[col];
    }
    int pair = ti * NUM_TYPES + tj;

    float d = edge_length[e];
    float s = d * 0.2f;                   // d / CUTOFF
    float x = 2.0f * s - 1.0f;
    float denom = 1.0f - s * s;
    float cut = (s < 1.0f) ? expf(1.0f - 1.0f / denom) : 0.0f;

    // Chebyshev T_0..T_10, scaled by envelope
    float T[NR];
    T[0] = 1.0f; T[1] = x;
    #pragma unroll
    for (int k = 2; k < NR; k++) T[k] = 2.0f * x * T[k - 1] - T[k - 2];
    #pragma unroll
    for (int k = 0; k < NR; k++) T[k] *= cut;

    // Per-edge contribution vector, register-resident.
    float c[SSTRIDE];

    // ---- radial features: slots 0..10 ----
    #pragma unroll
    for (int n = 0; n < NR; n++) {
        float acc = 0.0f;
        #pragma unroll
        for (int b = 0; b < NR; b++)
            acc = fmaf(T[b], crs[(b * NR + n) * 16 + pair], acc);
        c[n] = acc;
    }

    // ---- angular features ----
    float af[NA];
    #pragma unroll
    for (int n = 0; n < NA; n++) {
        float acc = 0.0f;
        #pragma unroll
        for (int b = 0; b < BA; b++)
            acc = fmaf(T[b], cas[(b * NA + n) * 16 + pair], acc);
        af[n] = acc;
    }

    float vx = edge_vec[e * 3 + 0];
    float vy = edge_vec[e * 3 + 1];
    float vz = edge_vec[e * 3 + 2];
    float inv = 1.0f / fmaxf(d, 1e-8f);
    float ux = vx * inv, uy = vy * inv, uz = vz * inv;

    // quad (symmetric; NOT traceless since edge_vec isn't unit-norm)
    float qxx = 1.5f * ux * ux - 0.5f;
    float qyy = 1.5f * uy * uy - 0.5f;
    float qzz = 1.5f * uz * uz - 0.5f;
    float qxy = 1.5f * ux * uy;
    float qxz = 1.5f * ux * uz;
    float qyz = 1.5f * uy * uz;

    // vec: slots 11..31, quad: slots 32..73
    #pragma unroll
    for (int n = 0; n < NA; n++) {
        float f = af[n];
        c[11 + n * 3 + 0] = f * ux;
        c[11 + n * 3 + 1] = f * uy;
        c[11 + n * 3 + 2] = f * uz;
        c[32 + n * 6 + 0] = f * qxx;
        c[32 + n * 6 + 1] = f * qyy;
        c[32 + n * 6 + 2] = f * qzz;
        c[32 + n * 6 + 3] = f * qxy;
        c[32 + n * 6 + 4] = f * qxz;
        c[32 + n * 6 + 5] = f * qyz;
    }
    c[74] = 0.0f; c[75] = 0.0f;

    float* base = g_scratch + row * SSTRIDE;   // 304B rows: 16B-aligned
    #pragma unroll
    for (int k = 0; k < SSTRIDE / 4; k++)
        red_add_v4(base + 4 * k, c[4 * k], c[4 * k + 1], c[4 * k + 2], c[4 * k + 3]);
}

__global__ void finalize_kernel(float* __restrict__ out, int N)
{
    int a = blockIdx.x * blockDim.x + threadIdx.x;
    if (a >= N) return;
    const float4* r4 = (const float4*)(g_scratch + a * SSTRIDE);
    float sc[SSTRIDE];
    #pragma unroll
    for (int k = 0; k < SSTRIDE / 4; k++) {
        float4 v = r4[k];
        sc[4 * k] = v.x; sc[4 * k + 1] = v.y; sc[4 * k + 2] = v.z; sc[4 * k + 3] = v.w;
    }
    float* o = out + a * 25;

    #pragma unroll
    for (int n = 0; n < NR; n++) o[n] = sc[n];

    #pragma unroll
    for (int n = 0; n < NA; n++) {
        float vx = sc[11 + n * 3 + 0];
        float vy = sc[11 + n * 3 + 1];
        float vz = sc[11 + n * 3 + 2];
        o[11 + n] = vx * vx + vy * vy + vz * vz;
    }
    #pragma unroll
    for (int n = 0; n < NA; n++) {
        float xx = sc[32 + n * 6 + 0];
        float yy = sc[32 + n * 6 + 1];
        float zz = sc[32 + n * 6 + 2];
        float xy = sc[32 + n * 6 + 3];
        float xz = sc[32 + n * 6 + 4];
        float yz = sc[32 + n * 6 + 5];
        o[18 + n] = xx * xx + yy * yy + zz * zz
                  + 2.0f * (xy * xy + xz * xz + yz * yz);
    }
}

extern "C" void kernel_launch(void* const* d_in, const int* in_sizes, int n_in,
                              void* d_out, int out_size)
{
    const void*  edge_index  = d_in[0];
    const float* edge_length = (const float*)d_in[1];
    const float* edge_vec    = (const float*)d_in[2];
    // d_in[3] = num_atoms scalar (unused; N derived from out_size)
    const void*  types       = d_in[4];
    const float* c_radial    = (const float*)d_in[5];
    const float* c_angular   = (const float*)d_in[6];

    int E = in_sizes[1];        // edge_length element count
    int N = out_size / 25;

    detect_dtype_kernel<<<1, 1>>>((const int*)edge_index);

    int zn4 = N * SSTRIDE / 4;
    zero_kernel<<<(zn4 + 511) / 512, 512>>>(zn4);

    edge_kernel<<<(E + 255) / 256, 256>>>(edge_index, edge_length, edge_vec,
                                          types, c_radial, c_angular, E);

    finalize_kernel<<<(N + 255) / 256, 256>>>((float*)d_out, N);
}